// round 17
// baseline (speedup 1.0000x reference)
#include <cuda_runtime.h>
#include <math.h>
#include <stdint.h>

// Problem constants
#define N_IMG     16
#define N_CH      3
#define NSLICE    (N_IMG * N_CH)          // 48
#define BINS      64
#define SLICE_ELEMS (1024 * 1024)

#define HTHREADS  128
#define BPS       9                               // 432 blocks (one wave at occ 3: 444 slots)
#define NBLOCKS   (NSLICE * BPS)
#define BLKS_PER_IMG (N_CH * BPS)                 // 27

// Counter phase: two u32 arrays [64][128] = 64 KB.
// MLP phase (consumers only): smem reused as floats:
//   [0..12288)      W1 j-half  [192][64]
//   [12288..16384)  W2         [128][32]
//   [16384..16576)  s_hist     [192]
//   [16576..16704)  s_h1       [128]
//   [16704..16832)  s_p        [128]
#define HSMEM_WORDS (2 * BINS * HTHREADS)         // 16384 (counter phase)
#define SMEM_FLOATS 16832
#define SMEM_BYTES  (SMEM_FLOATS * 4)             // 67328 B; 3 per SM = 202 KB, fits

// Params layout (in_ch,out_ch row-major), per reference
#define P_W1 0
#define P_B1 24576
#define P_W2 24704
#define P_B2 28800
#define P_G  28832
#define P_TOTAL 28833

#define DEPTH 8
#define WARM_BLOCKS 16

__device__ float g_part[NBLOCKS * BINS];
__device__ int   g_done[N_IMG];    // zero-init; consumer resets after observing 27
__device__ float g_sink;

__global__ __launch_bounds__(HTHREADS, 3)
void fused_kernel(const float* __restrict__ img,
                  const float* __restrict__ params,
                  float* __restrict__ out) {
    extern __shared__ unsigned int hh[];
    const int tid = threadIdx.x;

    const int slice = blockIdx.x / BPS;
    const int chunk = blockIdx.x % BPS;
    const int image = blockIdx.x / BLKS_PER_IMG;
    const float4* base = reinterpret_cast<const float4*>(img + (size_t)slice * SLICE_ELEMS);
    const int n4   = SLICE_ELEMS / 4;                 // 262144
    const int per  = (n4 + BPS - 1) / BPS;            // 29128
    const int start = chunk * per;
    const int end   = min(start + per, n4);

    // ---- Prefetch FIRST batch before zeroing ----
    int i = start + tid;
    float4 A[DEPTH], B[DEPTH];
    bool hasA = (i + (DEPTH - 1) * HTHREADS < end);
    if (hasA) {
        #pragma unroll
        for (int u = 0; u < DEPTH; u++) A[u] = __ldcs(base + i + u * HTHREADS);
    }

    // ---- First 16 blocks: warm L2 with params for the consumer staging ----
    if (blockIdx.x < WARM_BLOCKS) {
        const int seg = (P_TOTAL + WARM_BLOCKS - 1) / WARM_BLOCKS;
        const int s0  = blockIdx.x * seg;
        const int s1  = min(s0 + seg, P_TOTAL);
        float acc = 0.0f;
        for (int p = s0 + tid; p < s1; p += HTHREADS)
            acc += __ldg(params + p);
        if (__float_as_uint(acc) == 0x7F800001u)   // never true
            g_sink = acc;
    }

    {
        uint4* z = reinterpret_cast<uint4*>(hh);
        #pragma unroll
        for (int q = tid; q < HSMEM_WORDS / 4; q += HTHREADS)
            z[q] = make_uint4(0u, 0u, 0u, 0u);
    }
    __syncthreads();

    unsigned int* pA = hh + tid;
    unsigned int* pB = hh + BINS * HTHREADS + tid;

#define PROCPAIR(vA, vB) { \
        int ba = (int)__fmul_rd((vA), 64.0f); \
        int bb = (int)__fmul_rd((vB), 64.0f); \
        unsigned int ca = pA[ba * HTHREADS]; \
        unsigned int cb = pB[bb * HTHREADS]; \
        pA[ba * HTHREADS] = ca + 1u; \
        pB[bb * HTHREADS] = cb + 1u; }
#define PROC(v4) { PROCPAIR((v4).x, (v4).y); PROCPAIR((v4).z, (v4).w); }

    while (hasA) {
        const int j = i + DEPTH * HTHREADS;
        const bool hasB = (j + (DEPTH - 1) * HTHREADS < end);
        if (hasB) {
            #pragma unroll
            for (int u = 0; u < DEPTH; u++) B[u] = __ldcs(base + j + u * HTHREADS);
        }
        #pragma unroll
        for (int u = 0; u < DEPTH; u++) PROC(A[u]);
        i = j;
        if (!hasB) break;
        const int k = j + DEPTH * HTHREADS;
        hasA = (k + (DEPTH - 1) * HTHREADS < end);
        if (hasA) {
            #pragma unroll
            for (int u = 0; u < DEPTH; u++) A[u] = __ldcs(base + k + u * HTHREADS);
        }
        #pragma unroll
        for (int u = 0; u < DEPTH; u++) PROC(B[u]);
        i = k;
    }
    for (; i < end; i += HTHREADS) {
        float4 a = __ldcs(base + i);
        PROC(a);
    }
#undef PROC
#undef PROCPAIR
    __syncthreads();

    // Epilogue: warp w (of 4) reduces bins 16w..16w+15.
    {
        const int wid  = tid >> 5;
        const int lane = tid & 31;
        #pragma unroll
        for (int r = 0; r < 16; r++) {
            const int b = wid * 16 + r;
            const unsigned int* ra = hh + b * HTHREADS;
            const unsigned int* rb = hh + BINS * HTHREADS + b * HTHREADS;
            unsigned int s = ra[lane] + ra[lane + 32] + ra[lane + 64] + ra[lane + 96]
                           + rb[lane] + rb[lane + 32] + rb[lane + 64] + rb[lane + 96];
            #pragma unroll
            for (int d = 16; d >= 1; d >>= 1)
                s += __shfl_down_sync(0xFFFFFFFFu, s, d);
            if (lane == 0)
                g_part[blockIdx.x * BINS + b] = (float)s;
        }
    }

    // ---- Producer handshake: publish g_part, bump per-image counter ----
    __threadfence();
    __syncthreads();
    if (tid == 0) atomicAdd(&g_done[image], 1);

    // ---- Consumers (one per image): in-place MLP ----
    if ((blockIdx.x % BLKS_PER_IMG) != 0) return;

    __syncthreads();   // epilogue smem reads complete before re-staging
    float* f      = reinterpret_cast<float*>(hh);
    float* s_w1   = f;              // [192][64] (j-half)
    float* s_w2   = f + 12288;      // [128][32]
    float* s_hist = f + 16384;      // [192]
    float* s_h1   = f + 16576;      // [128]
    float* s_p    = f + 16704;      // [128]

    // Stage W1 half 0 (cols 0..63) + W2 while other producers drain (L2-warm)
    #pragma unroll 8
    for (int t = tid; t < 12288; t += HTHREADS)
        s_w1[t] = __ldg(params + P_W1 + (t >> 6) * 128 + (t & 63));
    #pragma unroll
    for (int t = tid; t < 1024; t += HTHREADS)
        reinterpret_cast<float4*>(s_w2)[t] = __ldg(reinterpret_cast<const float4*>(params + P_W2) + t);

    // Acquire-spin for all 27 producer blocks of this image
    if (tid == 0) {
        int v;
        do {
            asm volatile("ld.acquire.gpu.s32 %0, [%1];" : "=r"(v) : "l"(&g_done[image]) : "memory");
        } while (v < BLKS_PER_IMG);
        g_done[image] = 0;          // sole reader; all adds complete
        __threadfence();
    }
    __syncthreads();

    // Reduce this image's 27 partials into s_hist[c*64+b]
    for (int c2 = tid; c2 < 192; c2 += HTHREADS) {
        int c = c2 >> 6;
        int b = c2 & 63;
        const float* p = g_part + ((image * 3 + c) * BPS) * BINS + b;
        float s = 0.0f;
        #pragma unroll
        for (int k = 0; k < BPS; k++) s += p[k * BINS];
        s_hist[c2] = s;
    }
    __syncthreads();

    // Layer 1, j-half 0: jj = tid&63, part = tid>>6 covers c in [part*96, part*96+96)
    {
        const int jj   = tid & 63;
        const int part = tid >> 6;
        float acc = 0.0f;
        #pragma unroll 16
        for (int c = part * 96; c < part * 96 + 96; c++)
            acc = fmaf(s_hist[c], s_w1[c * 64 + jj], acc);
        s_p[part * 64 + jj] = acc;
    }
    __syncthreads();
    if (tid < 64)
        s_h1[tid] = fmaxf(s_p[tid] + s_p[64 + tid] + __ldg(params + P_B1 + tid), 0.0f);
    __syncthreads();

    // Re-stage W1 half 1 (cols 64..127) from L2
    #pragma unroll 8
    for (int t = tid; t < 12288; t += HTHREADS)
        s_w1[t] = __ldg(params + P_W1 + (t >> 6) * 128 + 64 + (t & 63));
    __syncthreads();

    // Layer 1, j-half 1
    {
        const int jj   = tid & 63;
        const int part = tid >> 6;
        float acc = 0.0f;
        #pragma unroll 16
        for (int c = part * 96; c < part * 96 + 96; c++)
            acc = fmaf(s_hist[c], s_w1[c * 64 + jj], acc);
        s_p[part * 64 + jj] = acc;
    }
    __syncthreads();
    if (tid < 64)
        s_h1[64 + tid] = fmaxf(s_p[tid] + s_p[64 + tid] + __ldg(params + P_B1 + 64 + tid), 0.0f);
    __syncthreads();

    // Layer 2: q = tid>>5 covers c in [q*32, q*32+32), k = tid&31
    {
        const int q = tid >> 5;
        const int k = tid & 31;
        float a = 0.0f;
        #pragma unroll
        for (int c = q * 32; c < q * 32 + 32; c++)
            a = fmaf(s_h1[c], s_w2[c * 32 + k], a);
        s_p[tid] = a;
    }
    __syncthreads();

    if (tid < 32) {
        float a = __ldg(params + P_B2 + tid) + __ldg(params + P_G)
                + s_p[tid] + s_p[32 + tid] + s_p[64 + tid] + s_p[96 + tid];
        out[image * 32 + tid] = 1.0f / (1.0f + expf(-a));
    }
}

extern "C" void kernel_launch(void* const* d_in, const int* in_sizes, int n_in,
                              void* d_out, int out_size) {
    const float* img    = (const float*)d_in[0];
    const float* params = (const float*)d_in[1];
    float* out          = (float*)d_out;

    static bool attr_set = false;
    if (!attr_set) {
        cudaFuncSetAttribute(fused_kernel, cudaFuncAttributeMaxDynamicSharedMemorySize, SMEM_BYTES);
        attr_set = true;
    }

    fused_kernel<<<NBLOCKS, HTHREADS, SMEM_BYTES>>>(img, params, out);
}